// round 1
// baseline (speedup 1.0000x reference)
#include <cuda_runtime.h>
#include <cuda_fp16.h>
#include <mma.h>

using namespace nvcuda;

#define BH      64        // batch*heads
#define SEQ     8192
#define DIM     64        // head dim
#define FEAT    128       // 2*DIM feature dim
#define NCHUNK  8
#define CHUNK   (SEQ / NCHUNK)   // 1024 rows per reduction chunk
#define SUB     64               // rows staged in smem per iteration

// ---- scratch (device globals: no allocation allowed) ----
__device__ float  g_kv_part[NCHUNK][BH][FEAT][DIM];   // per-chunk partial KV
__device__ float  g_ks_part[NCHUNK][BH][FEAT];        // per-chunk partial Ksum
__device__ __align__(32) __half g_kvh[BH][FEAT][80];  // reduced: cols 0..63 KV, 64 Ksum, 65..79 zero

// =====================================================================
// Kernel A: partial KV = phi(K)^T @ V over a 1024-row chunk, + Ksum
// grid (NCHUNK, BH), 256 threads (8 warps in a 4x2 d/m grid)
// =====================================================================
__global__ __launch_bounds__(256) void kv_partial_kernel(const float* __restrict__ Kin,
                                                         const float* __restrict__ Vin) {
    const int chunk = blockIdx.x;
    const int bh    = blockIdx.y;
    const int tid   = threadIdx.x;
    const int warp  = tid >> 5;
    const int wd    = warp >> 1;   // 0..3 -> 32 feature rows each
    const int wm    = warp & 1;    // 0..1 -> 32 V cols each

    __shared__ __align__(32) __half Kf_s[SUB][136];  // phi(K): 128 features + pad
    __shared__ __align__(32) __half V_s [SUB][72];

    wmma::fragment<wmma::accumulator, 16, 16, 16, float> acc[4];
#pragma unroll
    for (int i = 0; i < 4; i++) wmma::fill_fragment(acc[i], 0.0f);
    float ksum = 0.0f;

    const size_t base = ((size_t)bh * SEQ + (size_t)chunk * CHUNK) * DIM;
    const float* Kp = Kin + base;
    const float* Vp = Vin + base;

    for (int sub = 0; sub < CHUNK / SUB; ++sub) {
        __syncthreads();   // previous iteration's readers done
#pragma unroll
        for (int i = tid; i < SUB * DIM; i += 256) {
            int r = i >> 6, c = i & 63;
            float kv = Kp[sub * SUB * DIM + i];
            Kf_s[r][c]      = __float2half(fmaxf(kv, 0.0f));
            Kf_s[r][c + 64] = __float2half(fmaxf(-kv, 0.0f));
            V_s[r][c]       = __float2half(Vp[sub * SUB * DIM + i]);
        }
        __syncthreads();

        // SIMT Ksum over this sub-tile (threads 0..127, one feature each)
        if (tid < FEAT) {
#pragma unroll
            for (int r = 0; r < SUB; r++) ksum += __half2float(Kf_s[r][tid]);
        }

        // KV[d,m] += sum_n Kf[n,d] * V[n,m]   (A = Kf^T -> col_major view)
#pragma unroll
        for (int ks = 0; ks < SUB / 16; ++ks) {
            wmma::fragment<wmma::matrix_a, 16, 16, 16, __half, wmma::col_major> a0, a1;
            wmma::fragment<wmma::matrix_b, 16, 16, 16, __half, wmma::row_major> b0, b1;
            wmma::load_matrix_sync(a0, &Kf_s[ks * 16][wd * 32],      136);
            wmma::load_matrix_sync(a1, &Kf_s[ks * 16][wd * 32 + 16], 136);
            wmma::load_matrix_sync(b0, &V_s[ks * 16][wm * 32],       72);
            wmma::load_matrix_sync(b1, &V_s[ks * 16][wm * 32 + 16],  72);
            wmma::mma_sync(acc[0], a0, b0, acc[0]);
            wmma::mma_sync(acc[1], a0, b1, acc[1]);
            wmma::mma_sync(acc[2], a1, b0, acc[2]);
            wmma::mma_sync(acc[3], a1, b1, acc[3]);
        }
    }

    float* op = &g_kv_part[chunk][bh][0][0];
#pragma unroll
    for (int ti = 0; ti < 2; ++ti)
#pragma unroll
        for (int tj = 0; tj < 2; ++tj)
            wmma::store_matrix_sync(op + (wd * 32 + ti * 16) * DIM + wm * 32 + tj * 16,
                                    acc[ti * 2 + tj], DIM, wmma::mem_row_major);
    if (tid < FEAT) g_ks_part[chunk][bh][tid] = ksum;
}

// =====================================================================
// Kernel B: reduce chunk partials -> fp16 B matrix [128 x 80]
// grid (BH), 256 threads
// =====================================================================
__global__ __launch_bounds__(256) void kv_reduce_kernel() {
    const int bh = blockIdx.x;
    const int tid = threadIdx.x;
    for (int idx = tid; idx < FEAT * DIM; idx += 256) {
        int d = idx >> 6, m = idx & 63;
        float s = 0.0f;
#pragma unroll
        for (int c = 0; c < NCHUNK; c++) s += g_kv_part[c][bh][d][m];
        g_kvh[bh][d][m] = __float2half(s);
    }
    for (int d = tid; d < FEAT; d += 256) {
        float s = 0.0f;
#pragma unroll
        for (int c = 0; c < NCHUNK; c++) s += g_ks_part[c][bh][d];
        g_kvh[bh][d][64] = __float2half(s);
#pragma unroll
        for (int p = 65; p < 80; p++) g_kvh[bh][d][p] = __float2half(0.0f);
    }
}

// =====================================================================
// Kernel C: out = (phi(Q) @ [KV | Ksum]) with divide epilogue
// grid (SEQ/128, BH), 320 threads (10 warps: 2 row-groups x 5 col-tiles)
// =====================================================================
__global__ __launch_bounds__(320) void out_kernel(const float* __restrict__ Qin,
                                                  float* __restrict__ Out) {
    const int nt  = blockIdx.x;
    const int bh  = blockIdx.y;
    const int tid = threadIdx.x;
    const int warp = tid >> 5;

    // union buffer: phase 1 = Qf fp16 [128][136] (34816B), phase 2 = C fp32 [128][80] (40960B)
    __shared__ __align__(32) char smbuf[128 * 80 * 4];
    __half (*qf)[136] = reinterpret_cast<__half(*)[136]>(smbuf);
    float  (*cs)[80]  = reinterpret_cast<float(*)[80]>(smbuf);

    const size_t qbase = ((size_t)bh * SEQ + (size_t)nt * 128) * DIM;
    const float* Qp = Qin + qbase;

    for (int i = tid; i < 128 * DIM; i += 320) {
        int r = i >> 6, c = i & 63;
        float q = Qp[i];
        qf[r][c]      = __float2half(fmaxf(q, 0.0f));
        qf[r][c + 64] = __float2half(fmaxf(-q, 0.0f));
    }
    __syncthreads();

    const int wm = warp % 5;   // 16-col tile of the 80-wide B
    const int wg = warp / 5;   // 64-row group of Q rows

    wmma::fragment<wmma::accumulator, 16, 16, 16, float> acc[4];
#pragma unroll
    for (int i = 0; i < 4; i++) wmma::fill_fragment(acc[i], 0.0f);

    const __half* Bb = &g_kvh[bh][0][0];
#pragma unroll
    for (int ks = 0; ks < FEAT / 16; ++ks) {
        wmma::fragment<wmma::matrix_b, 16, 16, 16, __half, wmma::row_major> b;
        wmma::load_matrix_sync(b, Bb + ks * 16 * 80 + wm * 16, 80);
#pragma unroll
        for (int t = 0; t < 4; ++t) {
            wmma::fragment<wmma::matrix_a, 16, 16, 16, __half, wmma::row_major> a;
            wmma::load_matrix_sync(a, &qf[wg * 64 + t * 16][ks * 16], 136);
            wmma::mma_sync(acc[t], a, b, acc[t]);
        }
    }
    __syncthreads();   // everyone done reading qf before cs overwrites it

#pragma unroll
    for (int t = 0; t < 4; ++t)
        wmma::store_matrix_sync(&cs[wg * 64 + t * 16][wm * 16], acc[t], 80, wmma::mem_row_major);
    __syncthreads();

    float* Op = Out + qbase;
    for (int i = tid; i < 128 * DIM; i += 320) {
        int r = i >> 6, c = i & 63;
        Op[i] = cs[r][c] / (cs[r][64] + 1e-6f);
    }
}

// =====================================================================
extern "C" void kernel_launch(void* const* d_in, const int* in_sizes, int n_in,
                              void* d_out, int out_size) {
    const float* Q = (const float*)d_in[0];
    const float* K = (const float*)d_in[1];
    const float* V = (const float*)d_in[2];
    float* O = (float*)d_out;

    dim3 gA(NCHUNK, BH);
    kv_partial_kernel<<<gA, 256>>>(K, V);
    kv_reduce_kernel<<<BH, 256>>>();
    dim3 gC(SEQ / 128, BH);
    out_kernel<<<gC, 320>>>(Q, O);
}

// round 2
// speedup vs baseline: 1.5971x; 1.5971x over previous
#include <cuda_runtime.h>
#include <cuda_fp16.h>
#include <mma.h>

using namespace nvcuda;

#define BH      64        // batch*heads
#define SEQ     8192
#define DIM     64        // head dim
#define FEAT    128       // 2*DIM feature dim
#define NCHUNK  16
#define CHUNK   (SEQ / NCHUNK)   // 512 rows per reduction chunk
#define SUB     64               // rows staged in smem per iteration
#define BW      80               // B-matrix width: 64 KV cols + 1 Ksum + 15 pad

// ---- scratch (device globals: no allocation allowed) ----
__device__ float  g_kv_part[NCHUNK][BH][FEAT][BW];    // per-chunk partial [KV | Ksum | 0]
__device__ __align__(32) __half g_kvh[BH][FEAT][BW];  // reduced fp16 B matrix

// =====================================================================
// Kernel A: partial [KV | Ksum] = phi(K)^T @ [V | 1 | 0] over a chunk
// grid (NCHUNK, BH), 256 threads (8 warps: 4 feature-groups x 2 V-col-groups)
// =====================================================================
__global__ __launch_bounds__(256) void kv_partial_kernel(const float* __restrict__ Kin,
                                                         const float* __restrict__ Vin) {
    const int chunk = blockIdx.x;
    const int bh    = blockIdx.y;
    const int tid   = threadIdx.x;
    const int warp  = tid >> 5;
    const int wd    = warp >> 1;   // 0..3 -> 32 feature rows each
    const int wm    = warp & 1;    // 0..1 -> 32 V cols each

    __shared__ __align__(16) __half Kf_s[SUB][136];  // phi(K): 128 features + pad
    __shared__ __align__(16) __half V_s [SUB][88];   // V | ones | zeros | pad

    // one-time init of the augmented V columns (64 = ones, 65..79 = zeros)
    for (int r = tid; r < SUB; r += 256) {
        V_s[r][64] = __float2half(1.0f);
#pragma unroll
        for (int p = 65; p < 80; p++) V_s[r][p] = __float2half(0.0f);
    }

    wmma::fragment<wmma::accumulator, 16, 16, 16, float> acc[4];
    wmma::fragment<wmma::accumulator, 16, 16, 16, float> accs[2];  // Ksum tile (wm==0 only)
#pragma unroll
    for (int i = 0; i < 4; i++) wmma::fill_fragment(acc[i], 0.0f);
#pragma unroll
    for (int i = 0; i < 2; i++) wmma::fill_fragment(accs[i], 0.0f);

    const size_t base = ((size_t)bh * SEQ + (size_t)chunk * CHUNK) * DIM;
    const float4* Kp4 = (const float4*)(Kin + base);
    const float4* Vp4 = (const float4*)(Vin + base);

    for (int sub = 0; sub < CHUNK / SUB; ++sub) {
        __syncthreads();   // previous iteration's readers done
#pragma unroll
        for (int i = tid; i < SUB * 16; i += 256) {   // 16 float4 per 64-col row
            int r = i >> 4, c4 = (i & 15) << 2;
            float4 k = Kp4[sub * SUB * 16 + i];
            float4 v = Vp4[sub * SUB * 16 + i];
            __half2* kp = (__half2*)&Kf_s[r][c4];
            __half2* kn = (__half2*)&Kf_s[r][c4 + 64];
            __half2* vp = (__half2*)&V_s[r][c4];
            kp[0] = __floats2half2_rn(fmaxf(k.x, 0.f), fmaxf(k.y, 0.f));
            kp[1] = __floats2half2_rn(fmaxf(k.z, 0.f), fmaxf(k.w, 0.f));
            kn[0] = __floats2half2_rn(fmaxf(-k.x, 0.f), fmaxf(-k.y, 0.f));
            kn[1] = __floats2half2_rn(fmaxf(-k.z, 0.f), fmaxf(-k.w, 0.f));
            vp[0] = __floats2half2_rn(v.x, v.y);
            vp[1] = __floats2half2_rn(v.z, v.w);
        }
        __syncthreads();

        // KV[d,m] += sum_n Kf[n,d] * Vaug[n,m]   (A = Kf^T -> col_major view)
#pragma unroll
        for (int ks = 0; ks < SUB / 16; ++ks) {
            wmma::fragment<wmma::matrix_a, 16, 16, 16, __half, wmma::col_major> a0, a1;
            wmma::fragment<wmma::matrix_b, 16, 16, 16, __half, wmma::row_major> b0, b1;
            wmma::load_matrix_sync(a0, &Kf_s[ks * 16][wd * 32],      136);
            wmma::load_matrix_sync(a1, &Kf_s[ks * 16][wd * 32 + 16], 136);
            wmma::load_matrix_sync(b0, &V_s[ks * 16][wm * 32],       88);
            wmma::load_matrix_sync(b1, &V_s[ks * 16][wm * 32 + 16],  88);
            wmma::mma_sync(acc[0], a0, b0, acc[0]);
            wmma::mma_sync(acc[1], a0, b1, acc[1]);
            wmma::mma_sync(acc[2], a1, b0, acc[2]);
            wmma::mma_sync(acc[3], a1, b1, acc[3]);
            if (wm == 0) {   // augmented tile: cols 64..79 (Ksum in col 64)
                wmma::fragment<wmma::matrix_b, 16, 16, 16, __half, wmma::row_major> b2;
                wmma::load_matrix_sync(b2, &V_s[ks * 16][64], 88);
                wmma::mma_sync(accs[0], a0, b2, accs[0]);
                wmma::mma_sync(accs[1], a1, b2, accs[1]);
            }
        }
    }

    float* op = &g_kv_part[chunk][bh][0][0];
#pragma unroll
    for (int ti = 0; ti < 2; ++ti)
#pragma unroll
        for (int tj = 0; tj < 2; ++tj)
            wmma::store_matrix_sync(op + (wd * 32 + ti * 16) * BW + wm * 32 + tj * 16,
                                    acc[ti * 2 + tj], BW, wmma::mem_row_major);
    if (wm == 0) {
        wmma::store_matrix_sync(op + (wd * 32) * BW + 64,      accs[0], BW, wmma::mem_row_major);
        wmma::store_matrix_sync(op + (wd * 32 + 16) * BW + 64, accs[1], BW, wmma::mem_row_major);
    }
}

// =====================================================================
// Kernel B: reduce chunk partials -> fp16 B matrix [128 x 80]
// grid (BH, 8), 256 threads
// =====================================================================
__global__ __launch_bounds__(256) void kv_reduce_kernel() {
    const int bh    = blockIdx.x;
    const int slice = blockIdx.y;                 // 8 slices of 1280 elems
    const int tid   = threadIdx.x;
    for (int idx = slice * 1280 + tid; idx < (slice + 1) * 1280; idx += 256) {
        float s = 0.0f;
#pragma unroll
        for (int c = 0; c < NCHUNK; c++) s += (&g_kv_part[c][bh][0][0])[idx];
        (&g_kvh[bh][0][0])[idx] = __float2half(s);
    }
}

// =====================================================================
// Kernel C: out = (phi(Q) @ [KV | Ksum]) with divide epilogue
// grid (SEQ/128, BH), 320 threads (10 warps: 2 row-groups x 5 col-tiles)
// =====================================================================
__global__ __launch_bounds__(320) void out_kernel(const float* __restrict__ Qin,
                                                  float* __restrict__ Out) {
    const int nt  = blockIdx.x;
    const int bh  = blockIdx.y;
    const int tid = threadIdx.x;
    const int warp = tid >> 5;

    // union buffer: phase 1 = Qf fp16 [128][136] (34816B), phase 2 = C fp32 [128][80] (40960B)
    __shared__ __align__(16) char smbuf[128 * BW * 4];
    __half (*qf)[136] = reinterpret_cast<__half(*)[136]>(smbuf);
    float  (*cs)[BW]  = reinterpret_cast<float(*)[BW]>(smbuf);

    const size_t qbase = ((size_t)bh * SEQ + (size_t)nt * 128) * DIM;
    const float4* Qp4 = (const float4*)(Qin + qbase);

    for (int i = tid; i < 128 * 16; i += 320) {   // 2048 float4
        int r = i >> 4, c4 = (i & 15) << 2;
        float4 q = Qp4[i];
        __half2* qp = (__half2*)&qf[r][c4];
        __half2* qn = (__half2*)&qf[r][c4 + 64];
        qp[0] = __floats2half2_rn(fmaxf(q.x, 0.f), fmaxf(q.y, 0.f));
        qp[1] = __floats2half2_rn(fmaxf(q.z, 0.f), fmaxf(q.w, 0.f));
        qn[0] = __floats2half2_rn(fmaxf(-q.x, 0.f), fmaxf(-q.y, 0.f));
        qn[1] = __floats2half2_rn(fmaxf(-q.z, 0.f), fmaxf(-q.w, 0.f));
    }
    __syncthreads();

    const int wm = warp % 5;   // 16-col tile of the 80-wide B
    const int wg = warp / 5;   // 64-row group of Q rows

    wmma::fragment<wmma::accumulator, 16, 16, 16, float> acc[4];
#pragma unroll
    for (int i = 0; i < 4; i++) wmma::fill_fragment(acc[i], 0.0f);

    const __half* Bb = &g_kvh[bh][0][0];
#pragma unroll
    for (int ks = 0; ks < FEAT / 16; ++ks) {
        wmma::fragment<wmma::matrix_b, 16, 16, 16, __half, wmma::row_major> b;
        wmma::load_matrix_sync(b, Bb + ks * 16 * BW + wm * 16, BW);
#pragma unroll
        for (int t = 0; t < 4; ++t) {
            wmma::fragment<wmma::matrix_a, 16, 16, 16, __half, wmma::row_major> a;
            wmma::load_matrix_sync(a, &qf[wg * 64 + t * 16][ks * 16], 136);
            wmma::mma_sync(acc[t], a, b, acc[t]);
        }
    }
    __syncthreads();   // everyone done reading qf before cs overwrites it

#pragma unroll
    for (int t = 0; t < 4; ++t)
        wmma::store_matrix_sync(&cs[wg * 64 + t * 16][wm * 16], acc[t], BW, wmma::mem_row_major);
    __syncthreads();

    float4* Op4 = (float4*)(Out + qbase);
    for (int i = tid; i < 128 * 16; i += 320) {
        int r = i >> 4, c4 = (i & 15) << 2;
        float inv = 1.0f / (cs[r][64] + 1e-6f);
        float4 o;
        o.x = cs[r][c4 + 0] * inv;
        o.y = cs[r][c4 + 1] * inv;
        o.z = cs[r][c4 + 2] * inv;
        o.w = cs[r][c4 + 3] * inv;
        Op4[i] = o;
    }
}

// =====================================================================
extern "C" void kernel_launch(void* const* d_in, const int* in_sizes, int n_in,
                              void* d_out, int out_size) {
    const float* Q = (const float*)d_in[0];
    const float* K = (const float*)d_in[1];
    const float* V = (const float*)d_in[2];
    float* O = (float*)d_out;

    dim3 gA(NCHUNK, BH);
    kv_partial_kernel<<<gA, 256>>>(K, V);
    dim3 gB(BH, 8);
    kv_reduce_kernel<<<gB, 256>>>();
    dim3 gC(SEQ / 128, BH);
    out_kernel<<<gC, 320>>>(Q, O);
}

// round 4
// speedup vs baseline: 2.2006x; 1.3779x over previous
#include <cuda_runtime.h>
#include <cuda_fp16.h>
#include <mma.h>

using namespace nvcuda;

#define BH      64        // batch*heads
#define SEQ     8192
#define DIM     64        // head dim
#define FEAT    128       // 2*DIM feature dim
#define NCHUNK  16
#define CHUNK   (SEQ / NCHUNK)   // 512 rows per reduction chunk
#define SUB     64               // rows staged in smem per iteration
#define BW      80               // B-matrix width: 64 KV cols + 1 Ksum + 15 pad

// ---- scratch (device globals: no allocation allowed) ----
__device__ float  g_kv_part[NCHUNK][BH][FEAT][BW];    // per-chunk partial [KV | Ksum | 0]
__device__ __align__(32) __half g_kvh[BH][FEAT][BW];  // reduced fp16 B matrix

// =====================================================================
// Kernel A: partial [KV | Ksum] = phi(K)^T @ [V | 1 | 0] over a chunk
// grid (NCHUNK, BH), 256 threads. Register double-buffered pipeline:
// LDG for sub+1 issued before MMA on sub.
// =====================================================================
__global__ __launch_bounds__(256) void kv_partial_kernel(const float* __restrict__ Kin,
                                                         const float* __restrict__ Vin) {
    const int chunk = blockIdx.x;
    const int bh    = blockIdx.y;
    const int tid   = threadIdx.x;
    const int warp  = tid >> 5;
    const int wd    = warp >> 1;   // 0..3 -> 32 feature rows each
    const int wm    = warp & 1;    // 0..1 -> 32 V cols each

    __shared__ __align__(16) __half Kf_s[SUB][136];  // phi(K): 128 features + pad
    __shared__ __align__(16) __half V_s [SUB][88];   // V | ones | zeros | pad

    // one-time init of the augmented V columns (64 = ones, 65..79 = zeros)
    for (int r = tid; r < SUB; r += 256) {
        V_s[r][64] = __float2half(1.0f);
#pragma unroll
        for (int p = 65; p < 80; p++) V_s[r][p] = __float2half(0.0f);
    }

    wmma::fragment<wmma::accumulator, 16, 16, 16, float> acc[4];
    wmma::fragment<wmma::accumulator, 16, 16, 16, float> accs[2];  // Ksum tile (wm==0 only)
#pragma unroll
    for (int i = 0; i < 4; i++) wmma::fill_fragment(acc[i], 0.0f);
#pragma unroll
    for (int i = 0; i < 2; i++) wmma::fill_fragment(accs[i], 0.0f);

    const size_t base = ((size_t)bh * SEQ + (size_t)chunk * CHUNK) * DIM;
    const float4* __restrict__ Kp4 = (const float4*)(Kin + base);
    const float4* __restrict__ Vp4 = (const float4*)(Vin + base);

    const int NF4 = SUB * 16;          // 1024 float4 per sub-tile per matrix
    float4 kreg[4], vreg[4];

    // prefetch sub 0
#pragma unroll
    for (int j = 0; j < 4; j++) {
        int i = tid + j * 256;
        kreg[j] = Kp4[i];
        vreg[j] = Vp4[i];
    }

    for (int sub = 0; sub < CHUNK / SUB; ++sub) {
        // convert register buffer -> smem (phi transform on the fly)
#pragma unroll
        for (int j = 0; j < 4; j++) {
            int i = tid + j * 256;
            int r = i >> 4, c4 = (i & 15) << 2;
            float4 k = kreg[j], v = vreg[j];
            __half2* kp = (__half2*)&Kf_s[r][c4];
            __half2* kn = (__half2*)&Kf_s[r][c4 + 64];
            __half2* vp = (__half2*)&V_s[r][c4];
            kp[0] = __floats2half2_rn(fmaxf(k.x, 0.f), fmaxf(k.y, 0.f));
            kp[1] = __floats2half2_rn(fmaxf(k.z, 0.f), fmaxf(k.w, 0.f));
            kn[0] = __floats2half2_rn(fmaxf(-k.x, 0.f), fmaxf(-k.y, 0.f));
            kn[1] = __floats2half2_rn(fmaxf(-k.z, 0.f), fmaxf(-k.w, 0.f));
            vp[0] = __floats2half2_rn(v.x, v.y);
            vp[1] = __floats2half2_rn(v.z, v.w);
        }
        __syncthreads();

        // issue next sub-tile's global loads NOW; latency overlaps the MMAs below
        if (sub + 1 < CHUNK / SUB) {
#pragma unroll
            for (int j = 0; j < 4; j++) {
                int i = tid + j * 256;
                kreg[j] = Kp4[(sub + 1) * NF4 + i];
                vreg[j] = Vp4[(sub + 1) * NF4 + i];
            }
        }

        // KV[d,m] += sum_n Kf[n,d] * Vaug[n,m]   (A = Kf^T -> col_major view)
#pragma unroll
        for (int ks = 0; ks < SUB / 16; ++ks) {
            wmma::fragment<wmma::matrix_a, 16, 16, 16, __half, wmma::col_major> a0, a1;
            wmma::fragment<wmma::matrix_b, 16, 16, 16, __half, wmma::row_major> b0, b1;
            wmma::load_matrix_sync(a0, &Kf_s[ks * 16][wd * 32],      136);
            wmma::load_matrix_sync(a1, &Kf_s[ks * 16][wd * 32 + 16], 136);
            wmma::load_matrix_sync(b0, &V_s[ks * 16][wm * 32],       88);
            wmma::load_matrix_sync(b1, &V_s[ks * 16][wm * 32 + 16],  88);
            wmma::mma_sync(acc[0], a0, b0, acc[0]);
            wmma::mma_sync(acc[1], a0, b1, acc[1]);
            wmma::mma_sync(acc[2], a1, b0, acc[2]);
            wmma::mma_sync(acc[3], a1, b1, acc[3]);
            if (wm == 0) {   // augmented tile: cols 64..79 (Ksum in col 64)
                wmma::fragment<wmma::matrix_b, 16, 16, 16, __half, wmma::row_major> b2;
                wmma::load_matrix_sync(b2, &V_s[ks * 16][64], 88);
                wmma::mma_sync(accs[0], a0, b2, accs[0]);
                wmma::mma_sync(accs[1], a1, b2, accs[1]);
            }
        }
        __syncthreads();
    }

    float* op = &g_kv_part[chunk][bh][0][0];
#pragma unroll
    for (int ti = 0; ti < 2; ++ti)
#pragma unroll
        for (int tj = 0; tj < 2; ++tj)
            wmma::store_matrix_sync(op + (wd * 32 + ti * 16) * BW + wm * 32 + tj * 16,
                                    acc[ti * 2 + tj], BW, wmma::mem_row_major);
    if (wm == 0) {
        wmma::store_matrix_sync(op + (wd * 32) * BW + 64,      accs[0], BW, wmma::mem_row_major);
        wmma::store_matrix_sync(op + (wd * 32 + 16) * BW + 64, accs[1], BW, wmma::mem_row_major);
    }
}

// =====================================================================
// Kernel B: reduce chunk partials -> fp16 B matrix [128 x 80]
// grid (BH, 8), 256 threads
// =====================================================================
__global__ __launch_bounds__(256) void kv_reduce_kernel() {
    const int bh    = blockIdx.x;
    const int slice = blockIdx.y;                 // 8 slices of 1280 elems
    const int tid   = threadIdx.x;
    for (int idx = slice * 1280 + tid; idx < (slice + 1) * 1280; idx += 256) {
        float s = 0.0f;
#pragma unroll
        for (int c = 0; c < NCHUNK; c++) s += (&g_kv_part[c][bh][0][0])[idx];
        (&g_kvh[bh][0][0])[idx] = __float2half(s);
    }
}

// =====================================================================
// Kernel C: out = (phi(Q) @ [KV | Ksum]) with divide epilogue
// 64 Q rows per CTA. B staged to smem. grid (SEQ/64, BH), 320 threads
// (10 warps: 5 col-tiles x 2 row-halves of 32 rows)
// =====================================================================
__global__ __launch_bounds__(320) void out_kernel(const float* __restrict__ Qin,
                                                  float* __restrict__ Out) {
    const int nt  = blockIdx.x;
    const int bh  = blockIdx.y;
    const int tid = threadIdx.x;
    const int warp = tid >> 5;

    // union buffer: phase 1 = Qf fp16 [64][136] (17408B), phase 2 = C fp32 [64][80] (20480B)
    __shared__ __align__(16) char smbuf[64 * BW * 4];
    __shared__ __align__(16) __half Bs[FEAT][BW];   // 20480B staged B matrix
    __half (*qf)[136] = reinterpret_cast<__half(*)[136]>(smbuf);
    float  (*cs)[BW]  = reinterpret_cast<float(*)[BW]>(smbuf);

    const size_t qbase = ((size_t)bh * SEQ + (size_t)nt * 64) * DIM;
    const float4* __restrict__ Qp4 = (const float4*)(Qin + qbase);

    // stage B (coalesced uint4) and Qf concurrently
    const uint4* __restrict__ Bg = (const uint4*)&g_kvh[bh][0][0];
    uint4* Bsv = (uint4*)&Bs[0][0];
    for (int i = tid; i < FEAT * BW * 2 / 16; i += 320)   // 1280 uint4
        Bsv[i] = Bg[i];

    for (int i = tid; i < 64 * 16; i += 320) {   // 1024 float4
        int r = i >> 4, c4 = (i & 15) << 2;
        float4 q = Qp4[i];
        __half2* qp = (__half2*)&qf[r][c4];
        __half2* qn = (__half2*)&qf[r][c4 + 64];
        qp[0] = __floats2half2_rn(fmaxf(q.x, 0.f), fmaxf(q.y, 0.f));
        qp[1] = __floats2half2_rn(fmaxf(q.z, 0.f), fmaxf(q.w, 0.f));
        qn[0] = __floats2half2_rn(fmaxf(-q.x, 0.f), fmaxf(-q.y, 0.f));
        qn[1] = __floats2half2_rn(fmaxf(-q.z, 0.f), fmaxf(-q.w, 0.f));
    }
    __syncthreads();

    const int wm = warp % 5;   // 16-col tile of the 80-wide B
    const int wg = warp / 5;   // 32-row half of the 64 Q rows

    wmma::fragment<wmma::accumulator, 16, 16, 16, float> acc[2];
#pragma unroll
    for (int i = 0; i < 2; i++) wmma::fill_fragment(acc[i], 0.0f);

#pragma unroll
    for (int ks = 0; ks < FEAT / 16; ++ks) {
        wmma::fragment<wmma::matrix_b, 16, 16, 16, __half, wmma::row_major> b;
        wmma::load_matrix_sync(b, &Bs[ks * 16][wm * 16], BW);
#pragma unroll
        for (int t = 0; t < 2; ++t) {
            wmma::fragment<wmma::matrix_a, 16, 16, 16, __half, wmma::row_major> a;
            wmma::load_matrix_sync(a, &qf[wg * 32 + t * 16][ks * 16], 136);
            wmma::mma_sync(acc[t], a, b, acc[t]);
        }
    }
    __syncthreads();   // everyone done reading qf before cs overwrites it

#pragma unroll
    for (int t = 0; t < 2; ++t)
        wmma::store_matrix_sync(&cs[wg * 32 + t * 16][wm * 16], acc[t], BW, wmma::mem_row_major);
    __syncthreads();

    float4* Op4 = (float4*)(Out + qbase);
    for (int i = tid; i < 64 * 16; i += 320) {
        int r = i >> 4, c4 = (i & 15) << 2;
        float inv = 1.0f / (cs[r][64] + 1e-6f);
        float4 o;
        o.x = cs[r][c4 + 0] * inv;
        o.y = cs[r][c4 + 1] * inv;
        o.z = cs[r][c4 + 2] * inv;
        o.w = cs[r][c4 + 3] * inv;
        Op4[i] = o;
    }
}

// =====================================================================
extern "C" void kernel_launch(void* const* d_in, const int* in_sizes, int n_in,
                              void* d_out, int out_size) {
    const float* Q = (const float*)d_in[0];
    const float* K = (const float*)d_in[1];
    const float* V = (const float*)d_in[2];
    float* O = (float*)d_out;

    dim3 gA(NCHUNK, BH);
    kv_partial_kernel<<<gA, 256>>>(K, V);
    dim3 gB(BH, 8);
    kv_reduce_kernel<<<gB, 256>>>();
    dim3 gC(SEQ / 64, BH);
    out_kernel<<<gC, 320>>>(Q, O);
}

// round 7
// speedup vs baseline: 2.6354x; 1.1976x over previous
#include <cuda_runtime.h>
#include <cuda_fp16.h>
#include <mma.h>

using namespace nvcuda;

#define BH      64        // batch*heads
#define SEQ     8192
#define DIM     64        // head dim
#define FEAT    128       // 2*DIM feature dim
#define NCHUNK  16
#define CHUNK   (SEQ / NCHUNK)   // 512 rows per reduction chunk
#define SUB     64               // rows staged in smem per iteration
#define BW      80               // B-matrix width: 64 KV cols + 1 Ksum + 15 pad
#define OSUB    64               // out kernel: rows per sub-tile
#define ONSUB   4                // out kernel: sub-tiles per CTA

// ---- scratch (device globals: no allocation allowed) ----
__device__ float  g_kv_part[NCHUNK][BH][FEAT][BW];    // per-chunk partial [KV | Ksum | 0]
__device__ __align__(32) __half g_kvh[BH][FEAT][BW];  // reduced fp16 B matrix

// =====================================================================
// Kernel A: partial [KV | Ksum] = phi(K)^T @ [V | 1 | 0] over a chunk
// grid (NCHUNK, BH), 256 threads. Register double-buffered pipeline.
// =====================================================================
__global__ __launch_bounds__(256) void kv_partial_kernel(const float* __restrict__ Kin,
                                                         const float* __restrict__ Vin) {
    const int chunk = blockIdx.x;
    const int bh    = blockIdx.y;
    const int tid   = threadIdx.x;
    const int warp  = tid >> 5;
    const int wd    = warp >> 1;   // 0..3 -> 32 feature rows each
    const int wm    = warp & 1;    // 0..1 -> 32 V cols each

    __shared__ __align__(16) __half Kf_s[SUB][136];  // phi(K): 128 features + pad
    __shared__ __align__(16) __half V_s [SUB][88];   // V | ones | zeros | pad

    for (int r = tid; r < SUB; r += 256) {
        V_s[r][64] = __float2half(1.0f);
#pragma unroll
        for (int p = 65; p < 80; p++) V_s[r][p] = __float2half(0.0f);
    }

    wmma::fragment<wmma::accumulator, 16, 16, 16, float> acc[4];
    wmma::fragment<wmma::accumulator, 16, 16, 16, float> accs[2];  // Ksum tile (wm==0 only)
#pragma unroll
    for (int i = 0; i < 4; i++) wmma::fill_fragment(acc[i], 0.0f);
#pragma unroll
    for (int i = 0; i < 2; i++) wmma::fill_fragment(accs[i], 0.0f);

    const size_t base = ((size_t)bh * SEQ + (size_t)chunk * CHUNK) * DIM;
    const float4* __restrict__ Kp4 = (const float4*)(Kin + base);
    const float4* __restrict__ Vp4 = (const float4*)(Vin + base);

    const int NF4 = SUB * 16;          // 1024 float4 per sub-tile per matrix
    float4 kreg[4], vreg[4];

#pragma unroll
    for (int j = 0; j < 4; j++) {
        int i = tid + j * 256;
        kreg[j] = Kp4[i];
        vreg[j] = Vp4[i];
    }

    for (int sub = 0; sub < CHUNK / SUB; ++sub) {
#pragma unroll
        for (int j = 0; j < 4; j++) {
            int i = tid + j * 256;
            int r = i >> 4, c4 = (i & 15) << 2;
            float4 k = kreg[j], v = vreg[j];
            __half2* kp = (__half2*)&Kf_s[r][c4];
            __half2* kn = (__half2*)&Kf_s[r][c4 + 64];
            __half2* vp = (__half2*)&V_s[r][c4];
            kp[0] = __floats2half2_rn(fmaxf(k.x, 0.f), fmaxf(k.y, 0.f));
            kp[1] = __floats2half2_rn(fmaxf(k.z, 0.f), fmaxf(k.w, 0.f));
            kn[0] = __floats2half2_rn(fmaxf(-k.x, 0.f), fmaxf(-k.y, 0.f));
            kn[1] = __floats2half2_rn(fmaxf(-k.z, 0.f), fmaxf(-k.w, 0.f));
            vp[0] = __floats2half2_rn(v.x, v.y);
            vp[1] = __floats2half2_rn(v.z, v.w);
        }
        __syncthreads();

        if (sub + 1 < CHUNK / SUB) {
#pragma unroll
            for (int j = 0; j < 4; j++) {
                int i = tid + j * 256;
                kreg[j] = Kp4[(sub + 1) * NF4 + i];
                vreg[j] = Vp4[(sub + 1) * NF4 + i];
            }
        }

#pragma unroll
        for (int ks = 0; ks < SUB / 16; ++ks) {
            wmma::fragment<wmma::matrix_a, 16, 16, 16, __half, wmma::col_major> a0, a1;
            wmma::fragment<wmma::matrix_b, 16, 16, 16, __half, wmma::row_major> b0, b1;
            wmma::load_matrix_sync(a0, &Kf_s[ks * 16][wd * 32],      136);
            wmma::load_matrix_sync(a1, &Kf_s[ks * 16][wd * 32 + 16], 136);
            wmma::load_matrix_sync(b0, &V_s[ks * 16][wm * 32],       88);
            wmma::load_matrix_sync(b1, &V_s[ks * 16][wm * 32 + 16],  88);
            wmma::mma_sync(acc[0], a0, b0, acc[0]);
            wmma::mma_sync(acc[1], a0, b1, acc[1]);
            wmma::mma_sync(acc[2], a1, b0, acc[2]);
            wmma::mma_sync(acc[3], a1, b1, acc[3]);
            if (wm == 0) {   // augmented tile: cols 64..79 (Ksum in col 64)
                wmma::fragment<wmma::matrix_b, 16, 16, 16, __half, wmma::row_major> b2;
                wmma::load_matrix_sync(b2, &V_s[ks * 16][64], 88);
                wmma::mma_sync(accs[0], a0, b2, accs[0]);
                wmma::mma_sync(accs[1], a1, b2, accs[1]);
            }
        }
        __syncthreads();
    }

    float* op = &g_kv_part[chunk][bh][0][0];
#pragma unroll
    for (int ti = 0; ti < 2; ++ti)
#pragma unroll
        for (int tj = 0; tj < 2; ++tj)
            wmma::store_matrix_sync(op + (wd * 32 + ti * 16) * BW + wm * 32 + tj * 16,
                                    acc[ti * 2 + tj], BW, wmma::mem_row_major);
    if (wm == 0) {
        wmma::store_matrix_sync(op + (wd * 32) * BW + 64,      accs[0], BW, wmma::mem_row_major);
        wmma::store_matrix_sync(op + (wd * 32 + 16) * BW + 64, accs[1], BW, wmma::mem_row_major);
    }
}

// =====================================================================
// Kernel B: reduce chunk partials -> fp16 B matrix [128 x 80]
// grid (BH, 8), 256 threads
// =====================================================================
__global__ __launch_bounds__(256) void kv_reduce_kernel() {
    const int bh    = blockIdx.x;
    const int slice = blockIdx.y;                 // 8 slices of 1280 elems
    const int tid   = threadIdx.x;
    for (int idx = slice * 1280 + tid; idx < (slice + 1) * 1280; idx += 256) {
        float s = 0.0f;
#pragma unroll
        for (int c = 0; c < NCHUNK; c++) s += (&g_kv_part[c][bh][0][0])[idx];
        (&g_kvh[bh][0][0])[idx] = __float2half(s);
    }
}

// =====================================================================
// Kernel C: out = (phi(Q) @ [KV | Ksum]) with divide epilogue
// 4 sub-tiles of 64 Q rows per CTA, register-prefetch pipelined.
// B staged to smem once. grid (SEQ/256, BH), 320 threads
// (10 warps: 5 col-tiles x 2 row-halves)
// =====================================================================
__global__ __launch_bounds__(320) void out_kernel(const float* __restrict__ Qin,
                                                  float* __restrict__ Out) {
    const int nt  = blockIdx.x;
    const int bh  = blockIdx.y;
    const int tid = threadIdx.x;
    const int warp = tid >> 5;

    __shared__ __align__(16) __half qf[OSUB][136];   // 17408 B
    __shared__ __align__(16) float  cs[OSUB][BW];    // 20480 B
    __shared__ __align__(16) __half Bs[FEAT][BW];    // 20480 B

    const size_t qbase = ((size_t)bh * SEQ + (size_t)nt * (OSUB * ONSUB)) * DIM;
    const float4* __restrict__ Qp4 = (const float4*)(Qin + qbase);
    float4* __restrict__ Op4 = (float4*)(Out + qbase);

    // stage B once (coalesced uint4), concurrent with first Q prefetch
    const uint4* __restrict__ Bg = (const uint4*)&g_kvh[bh][0][0];
    uint4* Bsv = (uint4*)&Bs[0][0];
    for (int i = tid; i < FEAT * BW * 2 / 16; i += 320)   // 1280 uint4
        Bsv[i] = Bg[i];

    float4 qreg[4];
    if (tid < 256) {
#pragma unroll
        for (int j = 0; j < 4; j++) qreg[j] = Qp4[tid + j * 256];
    }

    const int wm = warp % 5;   // 16-col tile of the 80-wide B
    const int wg = warp / 5;   // 32-row half of the 64-row sub-tile

    for (int s = 0; s < ONSUB; ++s) {
        // convert register buffer -> qf (phi transform)
        if (tid < 256) {
#pragma unroll
            for (int j = 0; j < 4; j++) {
                int i = tid + j * 256;
                int r = i >> 4, c4 = (i & 15) << 2;
                float4 q = qreg[j];
                __half2* qp = (__half2*)&qf[r][c4];
                __half2* qn = (__half2*)&qf[r][c4 + 64];
                qp[0] = __floats2half2_rn(fmaxf(q.x, 0.f), fmaxf(q.y, 0.f));
                qp[1] = __floats2half2_rn(fmaxf(q.z, 0.f), fmaxf(q.w, 0.f));
                qn[0] = __floats2half2_rn(fmaxf(-q.x, 0.f), fmaxf(-q.y, 0.f));
                qn[1] = __floats2half2_rn(fmaxf(-q.z, 0.f), fmaxf(-q.w, 0.f));
            }
        }
        __syncthreads();

        // prefetch next sub-tile's Q; latency hides under the MMAs
        if (s + 1 < ONSUB && tid < 256) {
#pragma unroll
            for (int j = 0; j < 4; j++)
                qreg[j] = Qp4[(s + 1) * (OSUB * 16) + tid + j * 256];
        }

        wmma::fragment<wmma::accumulator, 16, 16, 16, float> acc[2];
#pragma unroll
        for (int i = 0; i < 2; i++) wmma::fill_fragment(acc[i], 0.0f);

#pragma unroll
        for (int ks = 0; ks < FEAT / 16; ++ks) {
            wmma::fragment<wmma::matrix_b, 16, 16, 16, __half, wmma::row_major> b;
            wmma::load_matrix_sync(b, &Bs[ks * 16][wm * 16], BW);
#pragma unroll
            for (int t = 0; t < 2; ++t) {
                wmma::fragment<wmma::matrix_a, 16, 16, 16, __half, wmma::row_major> a;
                wmma::load_matrix_sync(a, &qf[wg * 32 + t * 16][ks * 16], 136);
                wmma::mma_sync(acc[t], a, b, acc[t]);
            }
        }
        __syncthreads();   // MMA done: qf free for next iter, cs free from prior epilogue

#pragma unroll
        for (int t = 0; t < 2; ++t)
            wmma::store_matrix_sync(&cs[wg * 32 + t * 16][wm * 16], acc[t], BW,
                                    wmma::mem_row_major);
        __syncthreads();

        // epilogue: divide by normalizer (col 64) and stream out
        for (int i = tid; i < OSUB * 16; i += 320) {
            int r = i >> 4, c4 = (i & 15) << 2;
            float inv = 1.0f / (cs[r][64] + 1e-6f);
            float4 o;
            o.x = cs[r][c4 + 0] * inv;
            o.y = cs[r][c4 + 1] * inv;
            o.z = cs[r][c4 + 2] * inv;
            o.w = cs[r][c4 + 3] * inv;
            Op4[s * (OSUB * 16) + i] = o;
        }
        // no trailing sync needed: next convert writes qf (not cs), and the
        // post-MMA sync next iteration orders cs reuse.
    }
}

// =====================================================================
extern "C" void kernel_launch(void* const* d_in, const int* in_sizes, int n_in,
                              void* d_out, int out_size) {
    const float* Q = (const float*)d_in[0];
    const float* K = (const float*)d_in[1];
    const float* V = (const float*)d_in[2];
    float* O = (float*)d_out;

    dim3 gA(NCHUNK, BH);
    kv_partial_kernel<<<gA, 256>>>(K, V);
    dim3 gB(BH, 8);
    kv_reduce_kernel<<<gB, 256>>>();
    dim3 gC(SEQ / (OSUB * ONSUB), BH);
    out_kernel<<<gC, 320>>>(Q, O);
}